// round 10
// baseline (speedup 1.0000x reference)
#include <cuda_runtime.h>
#include <cuda_fp16.h>

#define D 96
#define HP 128                             // padded fp16 row (256B, 2 lines)
#define NMAX 50000
#define EMAX 800000
#define SCAN_B 512
#define NSCANBLK ((NMAX + SCAN_B - 1) / SCAN_B)   // 98

typedef unsigned long long ull;

// ---------------- scratch (static device globals; no allocation) ----------
__device__ int    g_counts[NMAX];          // zero at load; re-zeroed by k_scanall
__device__ int    g_rowptr[NMAX + 1];
__device__ int    g_cursor[NMAX];
__device__ float  g_dinv[NMAX];
__device__ int4   g_adj4[EMAX / 2 + 1];    // pairs of {src, bitcast(norm)}
__device__ __half g_hh[(size_t)NMAX * HP]; // GEMM out, fp16 padded; pad stays 0
__device__ float  g_h2[(size_t)NMAX * D];  // agg out / GEMM2 in (fp32)
__device__ int    g_blockSums[NSCANBLK + 2];
__device__ int    g_bar0, g_bar1, g_bar2;  // grid barrier counters (reset by agg1)

// ---------------- packed f32x2 helpers -------------------------------------
__device__ __forceinline__ ull pack2(float lo, float hi) {
    ull r; asm("mov.b64 %0, {%1, %2};" : "=l"(r) : "f"(lo), "f"(hi)); return r;
}
__device__ __forceinline__ void unpack2(ull v, float& lo, float& hi) {
    asm("mov.b64 {%0, %1}, %2;" : "=f"(lo), "=f"(hi) : "l"(v));
}
__device__ __forceinline__ void ffma2(ull& d, ull a, ull b) {
    asm("fma.rn.f32x2 %0, %1, %2, %0;" : "+l"(d) : "l"(a), "l"(b));
}

// ---------------- fused hist + scan + scatter (3 grid barriers, 98 blocks) --
__global__ __launch_bounds__(SCAN_B) void k_scanall(const int* __restrict__ ei,
                                                    int n, int nb, int E) {
    __shared__ int wsum[16];
    __shared__ int sbase;
    int tidb = threadIdx.x;
    int i = blockIdx.x * SCAN_B + tidb;
    int lane = tidb & 31, wid = tidb >> 5;
    int gstride = nb * SCAN_B;

    // phase 0: degree histogram
    for (int e = blockIdx.x * SCAN_B + tidb; e < E; e += gstride)
        atomicAdd(&g_counts[ei[E + e]], 1);
    __threadfence();
    __syncthreads();
    if (tidb == 0) {
        atomicAdd(&g_bar0, 1);
        while (*(volatile int*)&g_bar0 < nb) { }
    }
    __syncthreads();

    // phase A: read counts, dinv, re-zero counts, block-local exclusive scan
    int v = 0;
    if (i < n) {
        v = g_counts[i];
        g_dinv[i] = rsqrtf((float)(v + 1));   // +1 self loop
        g_counts[i] = 0;                      // restore invariant
    }
    int x = v;
#pragma unroll
    for (int o = 1; o < 32; o <<= 1) {
        int t = __shfl_up_sync(0xFFFFFFFFu, x, o);
        if (lane >= o) x += t;
    }
    if (lane == 31) wsum[wid] = x;
    __syncthreads();
    if (wid == 0) {
        int s = (lane < 16) ? wsum[lane] : 0;
#pragma unroll
        for (int o = 1; o < 16; o <<= 1) {
            int t = __shfl_up_sync(0xFFFFFFFFu, s, o);
            if (lane >= o) s += t;
        }
        if (lane < 16) wsum[lane] = s;
    }
    __syncthreads();
    int wbase = (wid > 0) ? wsum[wid - 1] : 0;
    if (i < n) g_rowptr[i] = wbase + x - v;          // block-local exclusive
    if (tidb == SCAN_B - 1) g_blockSums[blockIdx.x] = wbase + x;
    __threadfence();
    __syncthreads();
    if (tidb == 0) {
        atomicAdd(&g_bar1, 1);
        while (*(volatile int*)&g_bar1 < nb) { }
    }
    __syncthreads();

    // phase B: cross-block prefix, finalize rowptr + cursor
    if (wid == 0) {
        int acc = 0;
        for (int b = lane; b < blockIdx.x; b += 32) acc += g_blockSums[b];
#pragma unroll
        for (int o = 16; o; o >>= 1) acc += __shfl_xor_sync(0xFFFFFFFFu, acc, o);
        if (lane == 0) sbase = acc;
    }
    __syncthreads();
    int rbase = sbase;
    if (i < n) {
        int val = g_rowptr[i] + rbase;
        g_rowptr[i] = val;
        g_cursor[i] = val;
    }
    if (blockIdx.x == nb - 1 && tidb == 0)
        g_rowptr[n] = rbase + g_blockSums[nb - 1];   // total = E
    __threadfence();
    __syncthreads();
    if (tidb == 0) {
        atomicAdd(&g_bar2, 1);
        while (*(volatile int*)&g_bar2 < nb) { }
    }
    __syncthreads();

    // phase C: scatter edges into CSR
    int2* adj = (int2*)g_adj4;
    for (int e = blockIdx.x * SCAN_B + tidb; e < E; e += gstride) {
        int s = ei[e];
        int d = ei[E + e];
        int pos = atomicAdd(&g_cursor[d], 1);
        float norm = g_dinv[s] * g_dinv[d];
        adj[pos] = make_int2(s, __float_as_int(norm));
    }
}

// ---------------- dense GEMM: Hh[N,HP] = X[N,96] @ W[96,96] (fp16 out) -----
// 8-feature x 4-row register tile. block: 192 threads, TM=64 nodes.
// tid -> f0=(tid%12)*8, p0=(tid/12)*2 (two row-pairs, f32x2 packed rows).
// smem: Ws 36KB + Xs2 24KB = 60KB. src_sel: 0 = Xext, 1 = g_h2. Out: g_hh.
#define TM 64
__global__ __launch_bounds__(192) void k_gemm(const float* __restrict__ Xext,
                                              const float* __restrict__ W,
                                              int n, int src_sel) {
    __shared__ __align__(16) float Ws[96 * 96];
    __shared__ __align__(16) ull Xs2[32][96];   // Xs2[p][k] = {X[2p][k], X[2p+1][k]}
    const float* X = src_sel ? (const float*)g_h2 : Xext;
    __half* Y = (__half*)g_hh;

    int tid = threadIdx.x;

    {
        const float4* Wv = (const float4*)W;
        float4* Wsv = (float4*)Ws;
        for (int i = tid; i < 96 * 96 / 4; i += 192) Wsv[i] = Wv[i];
    }

    int n0 = blockIdx.x * TM;
    int rows = min(TM, n - n0);
    float* Xsf = (float*)&Xs2[0][0];
    for (int i = tid; i < TM * 96; i += 192) {
        int m = i / 96, k = i % 96;     // coalesced global read
        float v = (m < rows) ? X[(size_t)(n0 + m) * 96 + k] : 0.f;
        Xsf[((m >> 1) * 96 + k) * 2 + (m & 1)] = v;
    }
    __syncthreads();

    int f0 = (tid % 12) * 8;
    int p0 = (tid / 12) * 2;

    ull acc[8][2];
#pragma unroll
    for (int f = 0; f < 8; f++) { acc[f][0] = 0ull; acc[f][1] = 0ull; }

#pragma unroll 4
    for (int k = 0; k < 96; k += 2) {
        float4 wa0 = *(const float4*)&Ws[k * 96 + f0];
        float4 wa1 = *(const float4*)&Ws[k * 96 + f0 + 4];
        float4 wb0 = *(const float4*)&Ws[(k + 1) * 96 + f0];
        float4 wb1 = *(const float4*)&Ws[(k + 1) * 96 + f0 + 4];
        ulonglong2 x0 = *(const ulonglong2*)&Xs2[p0][k];
        ulonglong2 x1 = *(const ulonglong2*)&Xs2[p0 + 1][k];

        ull pa[8], pb[8];
        pa[0] = pack2(wa0.x, wa0.x); pa[1] = pack2(wa0.y, wa0.y);
        pa[2] = pack2(wa0.z, wa0.z); pa[3] = pack2(wa0.w, wa0.w);
        pa[4] = pack2(wa1.x, wa1.x); pa[5] = pack2(wa1.y, wa1.y);
        pa[6] = pack2(wa1.z, wa1.z); pa[7] = pack2(wa1.w, wa1.w);
        pb[0] = pack2(wb0.x, wb0.x); pb[1] = pack2(wb0.y, wb0.y);
        pb[2] = pack2(wb0.z, wb0.z); pb[3] = pack2(wb0.w, wb0.w);
        pb[4] = pack2(wb1.x, wb1.x); pb[5] = pack2(wb1.y, wb1.y);
        pb[6] = pack2(wb1.z, wb1.z); pb[7] = pack2(wb1.w, wb1.w);

#pragma unroll
        for (int f = 0; f < 8; f++) {
            ffma2(acc[f][0], x0.x, pa[f]);
            ffma2(acc[f][0], x0.y, pb[f]);
            ffma2(acc[f][1], x1.x, pa[f]);
            ffma2(acc[f][1], x1.y, pb[f]);
        }
    }

    union H4 { __half2 h2[4]; uint4 u; };

#pragma unroll
    for (int p = 0; p < 2; p++) {
        int m0 = (p0 + p) * 2;
        float lo[8], hi[8];
#pragma unroll
        for (int f = 0; f < 8; f++) unpack2(acc[f][p], lo[f], hi[f]);
        if (n0 + m0 < n) {
            H4 s;
            s.h2[0] = __floats2half2_rn(lo[0], lo[1]);
            s.h2[1] = __floats2half2_rn(lo[2], lo[3]);
            s.h2[2] = __floats2half2_rn(lo[4], lo[5]);
            s.h2[3] = __floats2half2_rn(lo[6], lo[7]);
            *(uint4*)&Y[(size_t)(n0 + m0) * HP + f0] = s.u;
        }
        if (n0 + m0 + 1 < n) {
            H4 s;
            s.h2[0] = __floats2half2_rn(hi[0], hi[1]);
            s.h2[1] = __floats2half2_rn(hi[2], hi[3]);
            s.h2[2] = __floats2half2_rn(hi[4], hi[5]);
            s.h2[3] = __floats2half2_rn(hi[6], hi[7]);
            *(uint4*)&Y[(size_t)(n0 + m0 + 1) * HP + f0] = s.u;
        }
    }
}

// ---------------- aggregation: one warp per node ---------------------------
// reads g_hh (fp16, stride HP); writes g_h2 (dst_sel=0) or out (dst_sel=1).
__global__ __launch_bounds__(256) void k_agg(const float* __restrict__ bias,
                                             const float* __restrict__ aptr,
                                             float* __restrict__ outExt,
                                             int n, int do_prelu, int dst_sel,
                                             int reset_bar) {
    if (reset_bar && blockIdx.x == 0 && threadIdx.x == 0) {
        g_bar0 = 0; g_bar1 = 0; g_bar2 = 0;   // for next replay's k_scanall
    }
    int warp = (blockIdx.x * blockDim.x + threadIdx.x) >> 5;
    int lane = threadIdx.x & 31;
    if (warp >= n) return;

    const __half2* hb = (const __half2*)g_hh;       // 64 half2 per row
    float* out = dst_sel ? outExt : (float*)g_h2;

    float dn = g_dinv[warp];
    float dn2 = dn * dn;
    const __half2* hr = hb + (size_t)warp * (HP / 2);
    float2 s0 = __half22float2(hr[lane]);
    float2 s1 = __half22float2(hr[32 + lane]);
    float a00 = s0.x * dn2, a01 = s0.y * dn2;
    float a10 = s1.x * dn2, a11 = s1.y * dn2;

    int e = g_rowptr[warp];
    int end = g_rowptr[warp + 1];
    const int2* adj = (const int2*)g_adj4;

    if ((e & 1) && e < end) {                 // align to int4 pairs
        int2 q = adj[e];
        const __half2* r = hb + (size_t)q.x * (HP / 2);
        float nn = __int_as_float(q.y);
        float2 u0 = __half22float2(r[lane]);
        float2 u1 = __half22float2(r[32 + lane]);
        a00 = fmaf(u0.x, nn, a00); a01 = fmaf(u0.y, nn, a01);
        a10 = fmaf(u1.x, nn, a10); a11 = fmaf(u1.y, nn, a11);
        e++;
    }
    for (; e + 1 < end; e += 2) {
        int4 q = *(const int4*)(adj + e);     // 2 edges, one broadcast LDG.128
        const __half2* r0 = hb + (size_t)q.x * (HP / 2);
        const __half2* r1 = hb + (size_t)q.z * (HP / 2);
        float n0 = __int_as_float(q.y);
        float n1 = __int_as_float(q.w);
        float2 u0 = __half22float2(r0[lane]);
        float2 u1 = __half22float2(r0[32 + lane]);
        float2 w0 = __half22float2(r1[lane]);
        float2 w1 = __half22float2(r1[32 + lane]);
        a00 = fmaf(u0.x, n0, a00); a01 = fmaf(u0.y, n0, a01);
        a10 = fmaf(u1.x, n0, a10); a11 = fmaf(u1.y, n0, a11);
        a00 = fmaf(w0.x, n1, a00); a01 = fmaf(w0.y, n1, a01);
        a10 = fmaf(w1.x, n1, a10); a11 = fmaf(w1.y, n1, a11);
    }
    if (e < end) {
        int2 q = adj[e];
        const __half2* r = hb + (size_t)q.x * (HP / 2);
        float nn = __int_as_float(q.y);
        float2 u0 = __half22float2(r[lane]);
        float2 u1 = __half22float2(r[32 + lane]);
        a00 = fmaf(u0.x, nn, a00); a01 = fmaf(u0.y, nn, a01);
        a10 = fmaf(u1.x, nn, a10); a11 = fmaf(u1.y, nn, a11);
    }

    const float2* b2 = (const float2*)bias;
    float2 bb0 = b2[lane];
    a00 += bb0.x; a01 += bb0.y;
    if (lane < 16) {
        float2 bb1 = b2[32 + lane];
        a10 += bb1.x; a11 += bb1.y;
    }
    if (do_prelu) {
        float a = aptr[0];
        a00 = (a00 > 0.f) ? a00 : a * a00;
        a01 = (a01 > 0.f) ? a01 : a * a01;
        a10 = (a10 > 0.f) ? a10 : a * a10;
        a11 = (a11 > 0.f) ? a11 : a * a11;
    }
    float2* o2 = (float2*)(out + (size_t)warp * 96);
    o2[lane] = make_float2(a00, a01);
    if (lane < 16) o2[32 + lane] = make_float2(a10, a11);
}

// ---------------- launch ---------------------------------------------------
extern "C" void kernel_launch(void* const* d_in, const int* in_sizes, int n_in,
                              void* d_out, int out_size) {
    const float* x  = (const float*)d_in[0];
    const int*   ei = (const int*)d_in[1];      // int32! (JAX x64 disabled)
    const float* W1 = (const float*)d_in[2];
    const float* b1 = (const float*)d_in[3];
    const float* a1 = (const float*)d_in[4];
    const float* W2 = (const float*)d_in[5];
    const float* b2 = (const float*)d_in[6];
    float*       out = (float*)d_out;

    int N = in_sizes[0] / D;
    int E = in_sizes[1] / 2;

    int nscan = (N + SCAN_B - 1) / SCAN_B;
    int gemm_blocks = (N + TM - 1) / TM;
    int agg_blocks = (N * 32 + 255) / 256;

    // 1) GEMM1 (clean, no fused hist)
    k_gemm<<<gemm_blocks, 192>>>(x, W1, N, 0);
    // 2) fused hist + scan (dinv, rowptr, cursor) + scatter
    k_scanall<<<nscan, SCAN_B>>>(ei, N, nscan, E);
    // 3) layer-1 aggregate + PReLU -> g_h2 (also resets barrier counters)
    k_agg<<<agg_blocks, 256>>>(b1, a1, out, N, 1, 0, 1);
    // 4) GEMM2: g_h2 @ W2 -> g_hh
    k_gemm<<<gemm_blocks, 192>>>(x /*unused*/, W2, N, 1);
    // 5) layer-2 aggregate -> out
    k_agg<<<agg_blocks, 256>>>(b2, a1, out, N, 0, 1, 0);
}

// round 11
// speedup vs baseline: 1.3412x; 1.3412x over previous
#include <cuda_runtime.h>
#include <cuda_fp16.h>
#include <mma.h>
using namespace nvcuda;

#define D 96
#define HP 128                             // padded fp16 row (256B, 2 lines)
#define NMAX 50000
#define EMAX 800000
#define SCAN_B 512
#define NSCANBLK ((NMAX + SCAN_B - 1) / SCAN_B)   // 98
#define TM 64
#define LDH 104                            // half stride for staged tiles (pad 8)

// gemm smem: Whi,Wlo (96*LDH each) + Xhi,Xlo (TM*LDH each), halves
#define GEMM_SMEM_HALVES (2 * 96 * LDH + 2 * TM * LDH)
#define GEMM_SMEM_BYTES (GEMM_SMEM_HALVES * 2)

// ---------------- scratch (static device globals; no allocation) ----------
__device__ int    g_counts[NMAX];          // zero at load; re-zeroed by k_scan1
__device__ int    g_rowptr[NMAX + 1];
__device__ int    g_cursor[NMAX];
__device__ float  g_dinv[NMAX];
__device__ int4   g_adj4[EMAX / 2 + 1];    // pairs of {src, bitcast(norm)}
__device__ __half g_hh[(size_t)NMAX * HP]; // GEMM out, fp16 padded; pad stays 0
__device__ float  g_h2[(size_t)NMAX * D];  // agg out / GEMM2 in (fp32)
__device__ int    g_blockSums[NSCANBLK + 2];

// ---------------- graph preprocessing (round-7 proven structure) -----------
__global__ void k_hist(const int* __restrict__ ei, int E) {
    int e = blockIdx.x * blockDim.x + threadIdx.x;
    if (e < E) atomicAdd(&g_counts[ei[E + e]], 1);
}

// block-local exclusive scan; fuses dinv and counts re-zero.
__global__ void k_scan1(int n) {
    __shared__ int wsum[16];
    int i = blockIdx.x * SCAN_B + threadIdx.x;
    int lane = threadIdx.x & 31, wid = threadIdx.x >> 5;
    int v = 0;
    if (i < n) {
        v = g_counts[i];
        g_dinv[i] = rsqrtf((float)(v + 1));   // +1 self loop
        g_counts[i] = 0;                      // restore invariant for replay
    }
    int x = v;
#pragma unroll
    for (int o = 1; o < 32; o <<= 1) {
        int t = __shfl_up_sync(0xFFFFFFFFu, x, o);
        if (lane >= o) x += t;
    }
    if (lane == 31) wsum[wid] = x;
    __syncthreads();
    if (wid == 0) {
        int s = (lane < 16) ? wsum[lane] : 0;
#pragma unroll
        for (int o = 1; o < 16; o <<= 1) {
            int t = __shfl_up_sync(0xFFFFFFFFu, s, o);
            if (lane >= o) s += t;
        }
        if (lane < 16) wsum[lane] = s;
    }
    __syncthreads();
    int base = (wid > 0) ? wsum[wid - 1] : 0;
    if (i < n) g_rowptr[i] = base + x - v;           // exclusive (block-local)
    if (threadIdx.x == SCAN_B - 1) g_blockSums[blockIdx.x] = base + x;
}

// cross-block prefix, finalize rowptr + cursor
__global__ void k_scan3(int n, int nb) {
    __shared__ int sbase;
    int bid = blockIdx.x;
    if (threadIdx.x < 32) {
        int lane = threadIdx.x;
        int acc = 0;
        for (int b = lane; b < bid; b += 32) acc += g_blockSums[b];
#pragma unroll
        for (int o = 16; o; o >>= 1) acc += __shfl_xor_sync(0xFFFFFFFFu, acc, o);
        if (lane == 0) sbase = acc;
    }
    __syncthreads();
    int base = sbase;
    int i = bid * SCAN_B + threadIdx.x;
    if (i < n) {
        int v = g_rowptr[i] + base;
        g_rowptr[i] = v;
        g_cursor[i] = v;
    }
    if (bid == nb - 1 && threadIdx.x == 0) {
        int tot = base;
        for (int b = bid; b < nb; b++) tot += g_blockSums[b];
        g_rowptr[n] = tot;                   // total = E
    }
}

__global__ void k_scatter(const int* __restrict__ ei, int E) {
    int e = blockIdx.x * blockDim.x + threadIdx.x;
    if (e < E) {
        int s = ei[e];
        int d = ei[E + e];
        int pos = atomicAdd(&g_cursor[d], 1);
        float norm = g_dinv[s] * g_dinv[d];
        ((int2*)g_adj4)[pos] = make_int2(s, __float_as_int(norm));
    }
}

// ---------------- tensor-core GEMM: Hh[N,HP] = X[N,96] @ W[96,96] ----------
// Split-fp16 compensated HMMA: X=Xhi+Xlo, W=Whi+Wlo (fp16 residual split);
// acc += Xhi*Whi + Xhi*Wlo + Xlo*Whi (fp32 accum) -> fp32-class accuracy.
// block: 256 threads (8 warps), TM=64 rows. warp w -> m-tile w&3, n-tiles
// (w>>2)*3 + {0,1,2} of 16x16. Output staged via smem overlay -> fp16 g_hh.
__global__ __launch_bounds__(256) void k_gemm(const float* __restrict__ Xext,
                                              const float* __restrict__ W,
                                              int n, int src_sel) {
    extern __shared__ __align__(16) __half sm[];
    __half* Whi = sm;
    __half* Wlo = Whi + 96 * LDH;
    __half* Xhi = Wlo + 96 * LDH;
    __half* Xlo = Xhi + TM * LDH;
    float*  Os  = (float*)Xhi;              // overlay after compute (24.6KB<=26.6KB)

    const float* X = src_sel ? (const float*)g_h2 : Xext;
    int tid = threadIdx.x;

    // stage W split (fp32 -> hi fp16 + residual fp16)
    for (int i = tid; i < 96 * 96; i += 256) {
        int r = i / 96, c = i % 96;
        float v = W[i];
        __half h = __float2half_rn(v);
        Whi[r * LDH + c] = h;
        Wlo[r * LDH + c] = __float2half_rn(v - __half2float(h));
    }
    // stage X split
    int n0 = blockIdx.x * TM;
    int rows = min(TM, n - n0);
    for (int i = tid; i < TM * 96; i += 256) {
        int r = i / 96, c = i % 96;
        float v = (r < rows) ? X[(size_t)(n0 + r) * 96 + c] : 0.f;
        __half h = __float2half_rn(v);
        Xhi[r * LDH + c] = h;
        Xlo[r * LDH + c] = __float2half_rn(v - __half2float(h));
    }
    __syncthreads();

    int warp = tid >> 5;
    int mi = warp & 3;                      // m tile 0..3
    int ng = warp >> 2;                     // n group 0..1 -> tiles ng*3+{0,1,2}

    wmma::fragment<wmma::accumulator, 16, 16, 16, float> acc[3];
#pragma unroll
    for (int j = 0; j < 3; j++) wmma::fill_fragment(acc[j], 0.f);

#pragma unroll
    for (int k = 0; k < 96; k += 16) {
        wmma::fragment<wmma::matrix_a, 16, 16, 16, __half, wmma::row_major> ahi, alo;
        wmma::load_matrix_sync(ahi, &Xhi[(mi * 16) * LDH + k], LDH);
        wmma::load_matrix_sync(alo, &Xlo[(mi * 16) * LDH + k], LDH);
#pragma unroll
        for (int j = 0; j < 3; j++) {
            int nn = (ng * 3 + j) * 16;
            wmma::fragment<wmma::matrix_b, 16, 16, 16, __half, wmma::row_major> bhi, blo;
            wmma::load_matrix_sync(bhi, &Whi[k * LDH + nn], LDH);
            wmma::load_matrix_sync(blo, &Wlo[k * LDH + nn], LDH);
            wmma::mma_sync(acc[j], ahi, bhi, acc[j]);
            wmma::mma_sync(acc[j], ahi, blo, acc[j]);
            wmma::mma_sync(acc[j], alo, bhi, acc[j]);
        }
    }
    __syncthreads();                        // X tiles no longer needed

    // store accumulators to smem (fp32, ld=96), then convert to fp16 global
#pragma unroll
    for (int j = 0; j < 3; j++) {
        int nn = (ng * 3 + j) * 16;
        wmma::store_matrix_sync(&Os[(mi * 16) * 96 + nn], acc[j], 96,
                                wmma::mem_row_major);
    }
    __syncthreads();

    union H4 { __half2 h2[4]; uint4 u; };
    for (int i = tid; i < TM * 12; i += 256) {   // 12 groups of 8 floats per row
        int r = i / 12, g = i % 12;
        if (r < rows) {
            const float* src = &Os[r * 96 + g * 8];
            H4 s;
            s.h2[0] = __floats2half2_rn(src[0], src[1]);
            s.h2[1] = __floats2half2_rn(src[2], src[3]);
            s.h2[2] = __floats2half2_rn(src[4], src[5]);
            s.h2[3] = __floats2half2_rn(src[6], src[7]);
            *(uint4*)&g_hh[(size_t)(n0 + r) * HP + g * 8] = s.u;
        }
    }
}

// ---------------- aggregation: one warp per node ---------------------------
// reads g_hh (fp16, stride HP); writes g_h2 (dst_sel=0) or out (dst_sel=1).
// 2 feature LDG/edge (half2 against zero-padded row) + 1 LDG.128 per 2 edges.
__global__ __launch_bounds__(256) void k_agg(const float* __restrict__ bias,
                                             const float* __restrict__ aptr,
                                             float* __restrict__ outExt,
                                             int n, int do_prelu, int dst_sel) {
    int warp = (blockIdx.x * blockDim.x + threadIdx.x) >> 5;
    int lane = threadIdx.x & 31;
    if (warp >= n) return;

    const __half2* hb = (const __half2*)g_hh;       // 64 half2 per row
    float* out = dst_sel ? outExt : (float*)g_h2;

    float dn = g_dinv[warp];
    float dn2 = dn * dn;
    const __half2* hr = hb + (size_t)warp * (HP / 2);
    float2 s0 = __half22float2(hr[lane]);
    float2 s1 = __half22float2(hr[32 + lane]);
    float a00 = s0.x * dn2, a01 = s0.y * dn2;
    float a10 = s1.x * dn2, a11 = s1.y * dn2;

    int e = g_rowptr[warp];
    int end = g_rowptr[warp + 1];
    const int2* adj = (const int2*)g_adj4;

    if ((e & 1) && e < end) {                 // align to int4 pairs
        int2 q = adj[e];
        const __half2* r = hb + (size_t)q.x * (HP / 2);
        float nn = __int_as_float(q.y);
        float2 u0 = __half22float2(r[lane]);
        float2 u1 = __half22float2(r[32 + lane]);
        a00 = fmaf(u0.x, nn, a00); a01 = fmaf(u0.y, nn, a01);
        a10 = fmaf(u1.x, nn, a10); a11 = fmaf(u1.y, nn, a11);
        e++;
    }
    for (; e + 1 < end; e += 2) {
        int4 q = *(const int4*)(adj + e);     // 2 edges, one broadcast LDG.128
        const __half2* r0 = hb + (size_t)q.x * (HP / 2);
        const __half2* r1 = hb + (size_t)q.z * (HP / 2);
        float n0 = __int_as_float(q.y);
        float n1 = __int_as_float(q.w);
        float2 u0 = __half22float2(r0[lane]);
        float2 u1 = __half22float2(r0[32 + lane]);
        float2 w0 = __half22float2(r1[lane]);
        float2 w1 = __half22float2(r1[32 + lane]);
        a00 = fmaf(u0.x, n0, a00); a01 = fmaf(u0.y, n0, a01);
        a10 = fmaf(u1.x, n0, a10); a11 = fmaf(u1.y, n0, a11);
        a00 = fmaf(w0.x, n1, a00); a01 = fmaf(w0.y, n1, a01);
        a10 = fmaf(w1.x, n1, a10); a11 = fmaf(w1.y, n1, a11);
    }
    if (e < end) {
        int2 q = adj[e];
        const __half2* r = hb + (size_t)q.x * (HP / 2);
        float nn = __int_as_float(q.y);
        float2 u0 = __half22float2(r[lane]);
        float2 u1 = __half22float2(r[32 + lane]);
        a00 = fmaf(u0.x, nn, a00); a01 = fmaf(u0.y, nn, a01);
        a10 = fmaf(u1.x, nn, a10); a11 = fmaf(u1.y, nn, a11);
    }

    const float2* b2 = (const float2*)bias;
    float2 bb0 = b2[lane];
    a00 += bb0.x; a01 += bb0.y;
    if (lane < 16) {
        float2 bb1 = b2[32 + lane];
        a10 += bb1.x; a11 += bb1.y;
    }
    if (do_prelu) {
        float a = aptr[0];
        a00 = (a00 > 0.f) ? a00 : a * a00;
        a01 = (a01 > 0.f) ? a01 : a * a01;
        a10 = (a10 > 0.f) ? a10 : a * a10;
        a11 = (a11 > 0.f) ? a11 : a * a11;
    }
    float2* o2 = (float2*)(out + (size_t)warp * 96);
    o2[lane] = make_float2(a00, a01);
    if (lane < 16) o2[32 + lane] = make_float2(a10, a11);
}

// ---------------- launch ---------------------------------------------------
extern "C" void kernel_launch(void* const* d_in, const int* in_sizes, int n_in,
                              void* d_out, int out_size) {
    const float* x  = (const float*)d_in[0];
    const int*   ei = (const int*)d_in[1];      // int32! (JAX x64 disabled)
    const float* W1 = (const float*)d_in[2];
    const float* b1 = (const float*)d_in[3];
    const float* a1 = (const float*)d_in[4];
    const float* W2 = (const float*)d_in[5];
    const float* b2 = (const float*)d_in[6];
    float*       out = (float*)d_out;

    int N = in_sizes[0] / D;
    int E = in_sizes[1] / 2;

    int nscan = (N + SCAN_B - 1) / SCAN_B;
    int gemm_blocks = (N + TM - 1) / TM;
    int agg_blocks = (N * 32 + 255) / 256;

    cudaFuncSetAttribute(k_gemm, cudaFuncAttributeMaxDynamicSharedMemorySize,
                         GEMM_SMEM_BYTES);

    // 1) GEMM1 (tensor cores)
    k_gemm<<<gemm_blocks, 256, GEMM_SMEM_BYTES>>>(x, W1, N, 0);
    // 2-5) graph preprocessing (round-7 proven structure)
    k_hist<<<(E + 255) / 256, 256>>>(ei, E);
    k_scan1<<<nscan, SCAN_B>>>(N);
    k_scan3<<<nscan, SCAN_B>>>(N, nscan);
    k_scatter<<<(E + 255) / 256, 256>>>(ei, E);
    // 6) layer-1 aggregate + PReLU -> g_h2
    k_agg<<<agg_blocks, 256>>>(b1, a1, out, N, 1, 0);
    // 7) GEMM2: g_h2 @ W2 -> g_hh
    k_gemm<<<gemm_blocks, 256, GEMM_SMEM_BYTES>>>(x /*unused*/, W2, N, 1);
    // 8) layer-2 aggregate -> out
    k_agg<<<agg_blocks, 256>>>(b2, a1, out, N, 0, 1);
}